// round 13
// baseline (speedup 1.0000x reference)
#include <cuda_runtime.h>
#include <math.h>

// ---------------------------------------------------------------------------
// VariationalDecoder: 168-step GRU decoder, B=1024, H=512, XP=256.
// 64 clusters x 2 CTAs x 256 threads. TB=16 batch rows per cluster.
// Each CTA owns 256 of 512 gate columns (1 col/thread, 3 gates, 16 rows).
// Doubles arithmetic intensity vs TB=8 (the measured L1tex-wavefront wall).
// h / x_prime halves exchanged via global staging + cluster.sync (2/step).
// ---------------------------------------------------------------------------

#define L_STEPS 168
#define BATCH   1024
#define HDIM    512
#define XPDIM   256
#define XLDIM   64
#define XEDIM   16
#define FEAT    592
#define TB      16
#define NCTA    128           // 64 clusters x 2
#define NT      256
#define OUTL    169
#define OUTC    24
#define OUT_ROW (OUTL * OUTC)            // 4056
#define NMU     ((size_t)BATCH * OUT_ROW)

// combined gate weights, k2-major: m<256 -> Whh k2=m; 256..383 -> Wih; pad 4.
// [m][jj=1536] float2 = {W[jj][2m], W[jj][2m+1]}
__device__ float2 g_WgC[388 * 1536];
// GEMM1: [q=148][n=256] float4 = rows 4q..4q+3 of Wtb for col n
__device__ float4 g_WtbP4[148 * 256];
// heads: [k2=256][oo=48] float2 (mu 0..23, lv 24..47)
__device__ float2 g_WhP[256 * 48];
// cross-CTA staging (per CTA: its OWN halves, read by the peer)
__device__ float g_hstage[NCTA][256 * 16];
__device__ float g_xstage[NCTA][128 * 16];

typedef unsigned long long u64;

__device__ __forceinline__ u64 ffma2(u64 a, u64 b, u64 c) {
    u64 d;
    asm("fma.rn.f32x2 %0, %1, %2, %3;" : "=l"(d) : "l"(a), "l"(b), "l"(c));
    return d;
}
__device__ __forceinline__ u64 splat2(float x) {
    u64 d;
    asm("mov.b64 %0, {%1, %1};" : "=l"(d) : "f"(x));
    return d;
}
__device__ __forceinline__ float2 unpack2(u64 v) {
    float2 f;
    asm("mov.b64 {%0, %1}, %2;" : "=f"(f.x), "=f"(f.y) : "l"(v));
    return f;
}
__device__ __forceinline__ float sigm(float x) { return 1.0f / (1.0f + expf(-x)); }

#define CLUSTER_SYNC() do { \
    asm volatile("barrier.cluster.arrive.aligned;" ::: "memory"); \
    asm volatile("barrier.cluster.wait.aligned;" ::: "memory"); \
} while (0)

// ---------------------------------------------------------------------------
// Prep (once per launch)
// ---------------------------------------------------------------------------
__global__ void prep_kernel(const float* __restrict__ Wih,
                            const float* __restrict__ Whh,
                            const float* __restrict__ Wmu,
                            const float* __restrict__ Wlv,
                            const float* __restrict__ Wtb) {
    int stride = gridDim.x * blockDim.x;
    int tid = blockIdx.x * blockDim.x + threadIdx.x;
    for (int idx = tid; idx < 388 * 1536; idx += stride) {
        int m = idx / 1536, jj = idx % 1536;
        float2 v = make_float2(0.f, 0.f);
        if (m < 256) {
            v = make_float2(Whh[jj * HDIM + 2 * m], Whh[jj * HDIM + 2 * m + 1]);
        } else if (m < 384) {
            int k2 = m - 256;
            v = make_float2(Wih[jj * XPDIM + 2 * k2], Wih[jj * XPDIM + 2 * k2 + 1]);
        }
        g_WgC[idx] = v;
    }
    for (int idx = tid; idx < 148 * 256; idx += stride) {
        int q = idx / 256, n = idx % 256;
        g_WtbP4[idx] = make_float4(Wtb[(4 * q) * XPDIM + n], Wtb[(4 * q + 1) * XPDIM + n],
                                   Wtb[(4 * q + 2) * XPDIM + n], Wtb[(4 * q + 3) * XPDIM + n]);
    }
    for (int idx = tid; idx < 256 * 48; idx += stride) {
        int k2 = idx / 48, oo = idx % 48;
        const float* Wh = (oo < 24) ? (Wmu + oo * HDIM) : (Wlv + (oo - 24) * HDIM);
        g_WhP[idx] = make_float2(Wh[2 * k2], Wh[2 * k2 + 1]);
    }
}

// ---------------------------------------------------------------------------
// FMA helpers: 8 FFMA2 = 16 rows x one weight scalar
// ---------------------------------------------------------------------------
__device__ __forceinline__ void fma8(const ulonglong2 (&F)[4], u64 w, u64 (&a)[8]) {
#pragma unroll
    for (int i = 0; i < 4; ++i) {
        a[2 * i]     = ffma2(F[i].x, w, a[2 * i]);
        a[2 * i + 1] = ffma2(F[i].y, w, a[2 * i + 1]);
    }
}
__device__ __forceinline__ void loadF(const float*& f, ulonglong2 (&F)[4]) {
#pragma unroll
    for (int i = 0; i < 4; ++i) F[i] = reinterpret_cast<const ulonglong2*>(f)[i];
    f += 16;
}

__device__ __forceinline__ void loadwb(float2 (&wb)[2][3], const float2* w) {
#pragma unroll
    for (int q = 0; q < 2; ++q)
#pragma unroll
        for (int g = 0; g < 3; ++g) wb[q][g] = w[q * 1536 + g * 512];
}

// one block = 2 k2 = 4 k rows, 3 gates, 16 batch rows (96 FFMA2)
__device__ __forceinline__ void proc2_16(const float*& f, const float2 (&wb)[2][3],
                                         u64 (&aR)[8], u64 (&aZ)[8], u64 (&aN)[8]) {
#pragma unroll
    for (int q = 0; q < 2; ++q) {
        ulonglong2 F0[4], F1[4];
        loadF(f, F0);
        loadF(f, F1);
        fma8(F0, splat2(wb[q][0].x), aR); fma8(F1, splat2(wb[q][0].y), aR);
        fma8(F0, splat2(wb[q][1].x), aZ); fma8(F1, splat2(wb[q][1].y), aZ);
        fma8(F0, splat2(wb[q][2].x), aN); fma8(F1, splat2(wb[q][2].y), aN);
    }
}

// GEMM1: one float4 = 4 k rows for this thread's column (32 FFMA2)
__device__ __forceinline__ void proc_q16(const float*& f, float4 wq, u64 (&a)[8]) {
    float wv[4] = {wq.x, wq.y, wq.z, wq.w};
#pragma unroll
    for (int kk = 0; kk < 4; ++kk) {
        ulonglong2 F[4];
        loadF(f, F);
        fma8(F, splat2(wv[kk]), a);
    }
}

// ---------------------------------------------------------------------------
// Heads: rank0 -> mu, rank1 -> lv. 192 thr: o=t%24, p=t/24 (8 K-partitions).
// Caller guarantees a preceding __syncthreads-equivalent barrier.
// ---------------------------------------------------------------------------
__device__ __forceinline__ void do_heads(const float* featT, float* red,
                                         float* __restrict__ out, int b0, int tstep,
                                         int rank,
                                         const float* __restrict__ bmu,
                                         const float* __restrict__ blv) {
    int t = threadIdx.x;
    if (t < 192) {
        int o = t % 24;
        int p = t / 24;
        u64 a[8];
#pragma unroll
        for (int i = 0; i < 8; ++i) a[i] = 0ull;
        const float2* w = g_WhP + (p * 32) * 48 + (rank * 24 + o);
        const float* f = featT + (p * 64) * 16;
#pragma unroll 2
        for (int k2 = 0; k2 < 32; ++k2) {
            ulonglong2 F0[4], F1[4];
            loadF(f, F0);
            loadF(f, F1);
            float2 wv = *w;
            fma8(F0, splat2(wv.x), a);
            fma8(F1, splat2(wv.y), a);
            w += 48;
        }
        u64* rp = reinterpret_cast<u64*>(red + t * 16);
#pragma unroll
        for (int i = 0; i < 8; ++i) rp[i] = a[i];
    }
    __syncthreads();
    if (t < 24) {
        float bias = rank ? blv[t] : bmu[t];
        float* obase = out + (rank ? NMU : 0) + (size_t)tstep * 24 + t;
#pragma unroll
        for (int r = 0; r < TB; ++r) {
            float s = bias;
#pragma unroll
            for (int p = 0; p < 8; ++p)
                s += red[(p * 24 + t) * 16 + r];
            obase[(size_t)(b0 + r) * OUT_ROW] = s;
        }
    }
}

// ---------------------------------------------------------------------------
// Main persistent kernel (cluster of 2 CTAs per batch group of 16)
// ---------------------------------------------------------------------------
extern "C" __global__ void __launch_bounds__(NT, 1) __cluster_dims__(2, 1, 1)
decoder_kernel(const float* __restrict__ xl, const float* __restrict__ xe,
               const float* __restrict__ z,
               const float* __restrict__ bih, const float* __restrict__ bhh,
               const float* __restrict__ bmu, const float* __restrict__ blv,
               const float* __restrict__ btb,
               float* __restrict__ out) {
    extern __shared__ __align__(16) float smem[];
    float* featT = smem;                         // [592][16] = 9472 floats
    float* xpT   = smem + FEAT * TB;             // [256][16] = 4096 floats
    float* red   = smem + FEAT * TB + XPDIM * TB;// 4096 floats

    const int t    = threadIdx.x;                // 0..255
    const int bid  = blockIdx.x;
    const int rank = bid & 1;
    const int b0   = (bid >> 1) * TB;
    const int c    = rank * 256 + t;             // gate column (0..511)

    // fused biases
    const float brz_r = bih[c]       + bhh[c];
    const float brz_z = bih[512 + c] + bhh[512 + c];
    const float bn_i  = bih[1024 + c];
    const float bn_h  = bhh[1024 + c];
    // GEMM1 split-K mapping: col j, K-half h1
    const int j1 = rank * 128 + (t & 127);
    const int h1 = t >> 7;
    const float btb_n = btb[rank * 128 + (t < 128 ? t : t - 128)];

    // featT <- z (each CTA loads full 512 cols of its 16 rows)
#pragma unroll
    for (int m = 0; m < 32; ++m) {
        int idx = t + NT * m;                    // 0..8191
        int r = idx >> 9, k = idx & 511;
        featT[k * 16 + r] = z[(size_t)(b0 + r) * HDIM + k];
    }
    __syncthreads();
    do_heads(featT, red, out, b0, 0, rank, bmu, blv);    // slot 0

    for (int step = 0; step < L_STEPS; ++step) {
        // ---- xl/xe tails ------------------------------------------------
#pragma unroll
        for (int m = 0; m < 4; ++m) {
            int idx = t + NT * m;                // 0..1023
            int r = idx >> 6, i = idx & 63;
            featT[(HDIM + i) * 16 + r] =
                xl[((size_t)(b0 + r) * L_STEPS + step) * XLDIM + i];
        }
        {
            int r = t >> 4, i = t & 15;          // 256 values
            featT[(HDIM + XLDIM + i) * 16 + r] =
                xe[((size_t)(b0 + r) * L_STEPS + step) * XEDIM + i];
        }
        __syncthreads();   // tails ready; also orders heads-red vs gemm1-red

        // ---- GEMM1 split-K x2 on own 128 cols ---------------------------
        {
            u64 a[8];
#pragma unroll
            for (int i = 0; i < 8; ++i) a[i] = 0ull;
            const float4* w = g_WtbP4 + (size_t)h1 * 74 * 256 + j1;
            const float* f = featT + h1 * 296 * 16;
            float4 wA = w[0], wB = w[256];
            w += 512;
#pragma unroll 1
            for (int q = 0; q < 72; q += 2) {
                float4 wC = w[0], wD = w[256];
                w += 512;
                proc_q16(f, wA, a);
                proc_q16(f, wB, a);
                wA = wC; wB = wD;
            }
            proc_q16(f, wA, a);
            proc_q16(f, wB, a);
            u64* rp = reinterpret_cast<u64*>(red + t * 16);
#pragma unroll
            for (int i = 0; i < 8; ++i) rp[i] = a[i];
        }
        __syncthreads();
        if (t < 128) {   // reduce halves, tanh, own xpT cols + stage
            float* dst = xpT + (rank * 128 + t) * 16;
            float* stg = g_xstage[bid] + t * 16;
#pragma unroll
            for (int r = 0; r < 16; ++r) {
                float s = red[t * 16 + r] + red[(128 + t) * 16 + r] + btb_n;
                float v = tanhf(s);
                dst[r] = v;
                stg[r] = v;
            }
        }
        __threadfence();   // xstage visible before sync #1 (taken mid-step)

        // ---- gates: hh phase first (K=512 over h) -----------------------
        u64 aR[8], aZ[8], aNi[8], aNh[8];
        {
            u64 br = splat2(brz_r), bz = splat2(brz_z), bn = splat2(bn_h);
#pragma unroll
            for (int p = 0; p < 8; ++p) { aR[p] = br; aZ[p] = bz; aNh[p] = bn; }
        }
        const float2* w = g_WgC + c;             // row stride 1536
        float2 wA[2][3], wB[2][3];
        loadwb(wA, w); w += 3072;
        {
            const float* f = featT;
#pragma unroll 1
            for (int bb = 0; bb < 64; ++bb) {    // 128 blocks = 256 k2
                loadwb(wB, w); w += 3072;
                proc2_16(f, wA, aR, aZ, aNh);
                loadwb(wA, w); w += 3072;
                proc2_16(f, wB, aR, aZ, aNh);
            }
            // wA now holds the first ih block (combined array, seamless)
        }

        // ---- exchange x_prime halves ------------------------------------
        CLUSTER_SYNC();                          // sync #1: xp visible
        if (t < 128) {
            const float4* src = reinterpret_cast<const float4*>(g_xstage[bid ^ 1] + t * 16);
            float4* dst = reinterpret_cast<float4*>(xpT + (((rank ^ 1) * 128) + t) * 16);
#pragma unroll
            for (int i = 0; i < 4; ++i) dst[i] = src[i];
        }
        __syncthreads();

        // ---- gates: ih phase (K=256 over x_prime) -----------------------
        {
            u64 bn = splat2(bn_i);
#pragma unroll
            for (int p = 0; p < 8; ++p) aNi[p] = bn;
        }
        {
            const float* f = xpT;
#pragma unroll 1
            for (int bb = 0; bb < 32; ++bb) {    // 64 blocks = 128 k2 (+pad)
                loadwb(wB, w); w += 3072;
                proc2_16(f, wA, aR, aZ, aNi);
                loadwb(wA, w); w += 3072;
                proc2_16(f, wB, aR, aZ, aNi);
            }
        }

        // ---- nonlinearity + h_new (own column c) ------------------------
        float hn[16];
#pragma unroll
        for (int p = 0; p < 8; ++p) {
            float2 rr = unpack2(aR[p]);
            float2 zz = unpack2(aZ[p]);
            float2 ni = unpack2(aNi[p]);
            float2 nh = unpack2(aNh[p]);
            float rx = sigm(rr.x), ry = sigm(rr.y);
            float zx = sigm(zz.x), zy = sigm(zz.y);
            float nx = tanhf(ni.x + rx * nh.x);
            float ny = tanhf(ni.y + ry * nh.y);
            float hx = featT[c * 16 + 2 * p];
            float hy = featT[c * 16 + 2 * p + 1];
            hn[2 * p]     = nx + zx * (hx - nx);
            hn[2 * p + 1] = ny + zy * (hy - ny);
        }
        {   // store own col locally + to stage (no reader conflicts remain)
            float4* dl = reinterpret_cast<float4*>(featT + c * 16);
            float4* ds = reinterpret_cast<float4*>(g_hstage[bid] + t * 16);
            const float4* hv = reinterpret_cast<const float4*>(hn);
#pragma unroll
            for (int i = 0; i < 4; ++i) { dl[i] = hv[i]; ds[i] = hv[i]; }
        }
        __threadfence();
        CLUSTER_SYNC();                          // sync #2: h visible
        {   // copy peer's h half
            const float4* src = reinterpret_cast<const float4*>(g_hstage[bid ^ 1] + t * 16);
            float4* dst = reinterpret_cast<float4*>(featT + (((rank ^ 1) * 256) + t) * 16);
#pragma unroll
            for (int i = 0; i < 4; ++i) dst[i] = src[i];
        }
        __syncthreads();

        do_heads(featT, red, out, b0, step + 1, rank, bmu, blv);
    }
}

// ---------------------------------------------------------------------------
extern "C" void kernel_launch(void* const* d_in, const int* in_sizes, int n_in,
                              void* d_out, int out_size) {
    const float* xl  = (const float*)d_in[0];   // x_l_seq   [1024,168,64]
    const float* xe  = (const float*)d_in[1];   // x_ext_seq [1024,168,16]
    const float* z   = (const float*)d_in[2];   // z_latent  [1024,512]
    const float* Wih = (const float*)d_in[3];   // [1536,256]
    const float* Whh = (const float*)d_in[4];   // [1536,512]
    const float* bih = (const float*)d_in[5];   // [1536]
    const float* bhh = (const float*)d_in[6];   // [1536]
    const float* Wmu = (const float*)d_in[7];   // [24,512]
    const float* bmu = (const float*)d_in[8];   // [24]
    const float* Wlv = (const float*)d_in[9];   // [24,512]
    const float* blv = (const float*)d_in[10];  // [24]
    const float* Wtb = (const float*)d_in[11];  // [592,256]
    const float* btb = (const float*)d_in[12];  // [256]
    float* out = (float*)d_out;                 // mu [1024,169,24] then lv

    const int smem_bytes = (FEAT * TB + XPDIM * TB + 4096) * 4;  // 70656
    cudaFuncSetAttribute((const void*)decoder_kernel,
                         cudaFuncAttributeMaxDynamicSharedMemorySize, smem_bytes);

    prep_kernel<<<256, 256>>>(Wih, Whh, Wmu, Wlv, Wtb);
    decoder_kernel<<<NCTA, NT, smem_bytes>>>(xl, xe, z, bih, bhh, bmu, blv, btb, out);
}

// round 14
// speedup vs baseline: 1.0001x; 1.0001x over previous
#include <cuda_runtime.h>
#include <math.h>

// ---------------------------------------------------------------------------
// VariationalDecoder: 168-step GRU decoder, B=1024, H=512, XP=256.
// 64 clusters x 2 CTAs x 256 threads. TB=16 batch rows per cluster.
// Each CTA owns 256 of 512 gate columns (1 col/thread, 3 gates, 16 rows).
// Doubles arithmetic intensity vs TB=8 (the measured L1tex-wavefront wall).
// h / x_prime halves exchanged via global staging + cluster.sync (2/step).
// ---------------------------------------------------------------------------

#define L_STEPS 168
#define BATCH   1024
#define HDIM    512
#define XPDIM   256
#define XLDIM   64
#define XEDIM   16
#define FEAT    592
#define TB      16
#define NCTA    128           // 64 clusters x 2
#define NT      256
#define OUTL    169
#define OUTC    24
#define OUT_ROW (OUTL * OUTC)            // 4056
#define NMU     ((size_t)BATCH * OUT_ROW)

// combined gate weights, k2-major: m<256 -> Whh k2=m; 256..383 -> Wih; pad 4.
// [m][jj=1536] float2 = {W[jj][2m], W[jj][2m+1]}
__device__ float2 g_WgC[388 * 1536];
// GEMM1: [q=148][n=256] float4 = rows 4q..4q+3 of Wtb for col n
__device__ float4 g_WtbP4[148 * 256];
// heads: [k2=256][oo=48] float2 (mu 0..23, lv 24..47)
__device__ float2 g_WhP[256 * 48];
// cross-CTA staging (per CTA: its OWN halves, read by the peer)
__device__ float g_hstage[NCTA][256 * 16];
__device__ float g_xstage[NCTA][128 * 16];

typedef unsigned long long u64;

__device__ __forceinline__ u64 ffma2(u64 a, u64 b, u64 c) {
    u64 d;
    asm("fma.rn.f32x2 %0, %1, %2, %3;" : "=l"(d) : "l"(a), "l"(b), "l"(c));
    return d;
}
__device__ __forceinline__ u64 splat2(float x) {
    u64 d;
    asm("mov.b64 %0, {%1, %1};" : "=l"(d) : "f"(x));
    return d;
}
__device__ __forceinline__ float2 unpack2(u64 v) {
    float2 f;
    asm("mov.b64 {%0, %1}, %2;" : "=f"(f.x), "=f"(f.y) : "l"(v));
    return f;
}
__device__ __forceinline__ float sigm(float x) { return 1.0f / (1.0f + expf(-x)); }

#define CLUSTER_SYNC() do { \
    asm volatile("barrier.cluster.arrive.aligned;" ::: "memory"); \
    asm volatile("barrier.cluster.wait.aligned;" ::: "memory"); \
} while (0)

// ---------------------------------------------------------------------------
// Prep (once per launch)
// ---------------------------------------------------------------------------
__global__ void prep_kernel(const float* __restrict__ Wih,
                            const float* __restrict__ Whh,
                            const float* __restrict__ Wmu,
                            const float* __restrict__ Wlv,
                            const float* __restrict__ Wtb) {
    int stride = gridDim.x * blockDim.x;
    int tid = blockIdx.x * blockDim.x + threadIdx.x;
    for (int idx = tid; idx < 388 * 1536; idx += stride) {
        int m = idx / 1536, jj = idx % 1536;
        float2 v = make_float2(0.f, 0.f);
        if (m < 256) {
            v = make_float2(Whh[jj * HDIM + 2 * m], Whh[jj * HDIM + 2 * m + 1]);
        } else if (m < 384) {
            int k2 = m - 256;
            v = make_float2(Wih[jj * XPDIM + 2 * k2], Wih[jj * XPDIM + 2 * k2 + 1]);
        }
        g_WgC[idx] = v;
    }
    for (int idx = tid; idx < 148 * 256; idx += stride) {
        int q = idx / 256, n = idx % 256;
        g_WtbP4[idx] = make_float4(Wtb[(4 * q) * XPDIM + n], Wtb[(4 * q + 1) * XPDIM + n],
                                   Wtb[(4 * q + 2) * XPDIM + n], Wtb[(4 * q + 3) * XPDIM + n]);
    }
    for (int idx = tid; idx < 256 * 48; idx += stride) {
        int k2 = idx / 48, oo = idx % 48;
        const float* Wh = (oo < 24) ? (Wmu + oo * HDIM) : (Wlv + (oo - 24) * HDIM);
        g_WhP[idx] = make_float2(Wh[2 * k2], Wh[2 * k2 + 1]);
    }
}

// ---------------------------------------------------------------------------
// FMA helpers: 8 FFMA2 = 16 rows x one weight scalar
// ---------------------------------------------------------------------------
__device__ __forceinline__ void fma8(const ulonglong2 (&F)[4], u64 w, u64 (&a)[8]) {
#pragma unroll
    for (int i = 0; i < 4; ++i) {
        a[2 * i]     = ffma2(F[i].x, w, a[2 * i]);
        a[2 * i + 1] = ffma2(F[i].y, w, a[2 * i + 1]);
    }
}
__device__ __forceinline__ void loadF(const float*& f, ulonglong2 (&F)[4]) {
#pragma unroll
    for (int i = 0; i < 4; ++i) F[i] = reinterpret_cast<const ulonglong2*>(f)[i];
    f += 16;
}

__device__ __forceinline__ void loadwb(float2 (&wb)[2][3], const float2* w) {
#pragma unroll
    for (int q = 0; q < 2; ++q)
#pragma unroll
        for (int g = 0; g < 3; ++g) wb[q][g] = w[q * 1536 + g * 512];
}

// one block = 2 k2 = 4 k rows, 3 gates, 16 batch rows (96 FFMA2)
__device__ __forceinline__ void proc2_16(const float*& f, const float2 (&wb)[2][3],
                                         u64 (&aR)[8], u64 (&aZ)[8], u64 (&aN)[8]) {
#pragma unroll
    for (int q = 0; q < 2; ++q) {
        ulonglong2 F0[4], F1[4];
        loadF(f, F0);
        loadF(f, F1);
        fma8(F0, splat2(wb[q][0].x), aR); fma8(F1, splat2(wb[q][0].y), aR);
        fma8(F0, splat2(wb[q][1].x), aZ); fma8(F1, splat2(wb[q][1].y), aZ);
        fma8(F0, splat2(wb[q][2].x), aN); fma8(F1, splat2(wb[q][2].y), aN);
    }
}

// GEMM1: one float4 = 4 k rows for this thread's column (32 FFMA2)
__device__ __forceinline__ void proc_q16(const float*& f, float4 wq, u64 (&a)[8]) {
    float wv[4] = {wq.x, wq.y, wq.z, wq.w};
#pragma unroll
    for (int kk = 0; kk < 4; ++kk) {
        ulonglong2 F[4];
        loadF(f, F);
        fma8(F, splat2(wv[kk]), a);
    }
}

// ---------------------------------------------------------------------------
// Heads: rank0 -> mu, rank1 -> lv. 192 thr: o=t%24, p=t/24 (8 K-partitions).
// Caller guarantees a preceding __syncthreads-equivalent barrier.
// ---------------------------------------------------------------------------
__device__ __forceinline__ void do_heads(const float* featT, float* red,
                                         float* __restrict__ out, int b0, int tstep,
                                         int rank,
                                         const float* __restrict__ bmu,
                                         const float* __restrict__ blv) {
    int t = threadIdx.x;
    if (t < 192) {
        int o = t % 24;
        int p = t / 24;
        u64 a[8];
#pragma unroll
        for (int i = 0; i < 8; ++i) a[i] = 0ull;
        const float2* w = g_WhP + (p * 32) * 48 + (rank * 24 + o);
        const float* f = featT + (p * 64) * 16;
#pragma unroll 2
        for (int k2 = 0; k2 < 32; ++k2) {
            ulonglong2 F0[4], F1[4];
            loadF(f, F0);
            loadF(f, F1);
            float2 wv = *w;
            fma8(F0, splat2(wv.x), a);
            fma8(F1, splat2(wv.y), a);
            w += 48;
        }
        u64* rp = reinterpret_cast<u64*>(red + t * 16);
#pragma unroll
        for (int i = 0; i < 8; ++i) rp[i] = a[i];
    }
    __syncthreads();
    if (t < 24) {
        float bias = rank ? blv[t] : bmu[t];
        float* obase = out + (rank ? NMU : 0) + (size_t)tstep * 24 + t;
#pragma unroll
        for (int r = 0; r < TB; ++r) {
            float s = bias;
#pragma unroll
            for (int p = 0; p < 8; ++p)
                s += red[(p * 24 + t) * 16 + r];
            obase[(size_t)(b0 + r) * OUT_ROW] = s;
        }
    }
}

// ---------------------------------------------------------------------------
// Main persistent kernel (cluster of 2 CTAs per batch group of 16)
// ---------------------------------------------------------------------------
extern "C" __global__ void __launch_bounds__(NT, 1) __cluster_dims__(2, 1, 1)
decoder_kernel(const float* __restrict__ xl, const float* __restrict__ xe,
               const float* __restrict__ z,
               const float* __restrict__ bih, const float* __restrict__ bhh,
               const float* __restrict__ bmu, const float* __restrict__ blv,
               const float* __restrict__ btb,
               float* __restrict__ out) {
    extern __shared__ __align__(16) float smem[];
    float* featT = smem;                         // [592][16] = 9472 floats
    float* xpT   = smem + FEAT * TB;             // [256][16] = 4096 floats
    float* red   = smem + FEAT * TB + XPDIM * TB;// 4096 floats

    const int t    = threadIdx.x;                // 0..255
    const int bid  = blockIdx.x;
    const int rank = bid & 1;
    const int b0   = (bid >> 1) * TB;
    const int c    = rank * 256 + t;             // gate column (0..511)

    // fused biases
    const float brz_r = bih[c]       + bhh[c];
    const float brz_z = bih[512 + c] + bhh[512 + c];
    const float bn_i  = bih[1024 + c];
    const float bn_h  = bhh[1024 + c];
    // GEMM1 split-K mapping: col j, K-half h1
    const int j1 = rank * 128 + (t & 127);
    const int h1 = t >> 7;
    const float btb_n = btb[rank * 128 + (t < 128 ? t : t - 128)];

    // featT <- z (each CTA loads full 512 cols of its 16 rows)
#pragma unroll
    for (int m = 0; m < 32; ++m) {
        int idx = t + NT * m;                    // 0..8191
        int r = idx >> 9, k = idx & 511;
        featT[k * 16 + r] = z[(size_t)(b0 + r) * HDIM + k];
    }
    __syncthreads();
    do_heads(featT, red, out, b0, 0, rank, bmu, blv);    // slot 0

    for (int step = 0; step < L_STEPS; ++step) {
        // ---- xl/xe tails ------------------------------------------------
#pragma unroll
        for (int m = 0; m < 4; ++m) {
            int idx = t + NT * m;                // 0..1023
            int r = idx >> 6, i = idx & 63;
            featT[(HDIM + i) * 16 + r] =
                xl[((size_t)(b0 + r) * L_STEPS + step) * XLDIM + i];
        }
        {
            int r = t >> 4, i = t & 15;          // 256 values
            featT[(HDIM + XLDIM + i) * 16 + r] =
                xe[((size_t)(b0 + r) * L_STEPS + step) * XEDIM + i];
        }
        __syncthreads();   // tails ready; also orders heads-red vs gemm1-red

        // ---- GEMM1 split-K x2 on own 128 cols ---------------------------
        {
            u64 a[8];
#pragma unroll
            for (int i = 0; i < 8; ++i) a[i] = 0ull;
            const float4* w = g_WtbP4 + (size_t)h1 * 74 * 256 + j1;
            const float* f = featT + h1 * 296 * 16;
            float4 wA = w[0], wB = w[256];
            w += 512;
#pragma unroll 1
            for (int q = 0; q < 72; q += 2) {
                float4 wC = w[0], wD = w[256];
                w += 512;
                proc_q16(f, wA, a);
                proc_q16(f, wB, a);
                wA = wC; wB = wD;
            }
            proc_q16(f, wA, a);
            proc_q16(f, wB, a);
            u64* rp = reinterpret_cast<u64*>(red + t * 16);
#pragma unroll
            for (int i = 0; i < 8; ++i) rp[i] = a[i];
        }
        __syncthreads();
        if (t < 128) {   // reduce halves, tanh, own xpT cols + stage
            float* dst = xpT + (rank * 128 + t) * 16;
            float* stg = g_xstage[bid] + t * 16;
#pragma unroll
            for (int r = 0; r < 16; ++r) {
                float s = red[t * 16 + r] + red[(128 + t) * 16 + r] + btb_n;
                float v = tanhf(s);
                dst[r] = v;
                stg[r] = v;
            }
        }
        __threadfence();   // xstage visible before sync #1 (taken mid-step)

        // ---- gates: hh phase first (K=512 over h) -----------------------
        u64 aR[8], aZ[8], aNi[8], aNh[8];
        {
            u64 br = splat2(brz_r), bz = splat2(brz_z), bn = splat2(bn_h);
#pragma unroll
            for (int p = 0; p < 8; ++p) { aR[p] = br; aZ[p] = bz; aNh[p] = bn; }
        }
        const float2* w = g_WgC + c;             // row stride 1536
        float2 wA[2][3], wB[2][3];
        loadwb(wA, w); w += 3072;
        {
            const float* f = featT;
#pragma unroll 1
            for (int bb = 0; bb < 64; ++bb) {    // 128 blocks = 256 k2
                loadwb(wB, w); w += 3072;
                proc2_16(f, wA, aR, aZ, aNh);
                loadwb(wA, w); w += 3072;
                proc2_16(f, wB, aR, aZ, aNh);
            }
            // wA now holds the first ih block (combined array, seamless)
        }

        // ---- exchange x_prime halves ------------------------------------
        CLUSTER_SYNC();                          // sync #1: xp visible
        if (t < 128) {
            const float4* src = reinterpret_cast<const float4*>(g_xstage[bid ^ 1] + t * 16);
            float4* dst = reinterpret_cast<float4*>(xpT + (((rank ^ 1) * 128) + t) * 16);
#pragma unroll
            for (int i = 0; i < 4; ++i) dst[i] = src[i];
        }
        __syncthreads();

        // ---- gates: ih phase (K=256 over x_prime) -----------------------
        {
            u64 bn = splat2(bn_i);
#pragma unroll
            for (int p = 0; p < 8; ++p) aNi[p] = bn;
        }
        {
            const float* f = xpT;
#pragma unroll 1
            for (int bb = 0; bb < 32; ++bb) {    // 64 blocks = 128 k2 (+pad)
                loadwb(wB, w); w += 3072;
                proc2_16(f, wA, aR, aZ, aNi);
                loadwb(wA, w); w += 3072;
                proc2_16(f, wB, aR, aZ, aNi);
            }
        }

        // ---- nonlinearity + h_new (own column c) ------------------------
        float hn[16];
#pragma unroll
        for (int p = 0; p < 8; ++p) {
            float2 rr = unpack2(aR[p]);
            float2 zz = unpack2(aZ[p]);
            float2 ni = unpack2(aNi[p]);
            float2 nh = unpack2(aNh[p]);
            float rx = sigm(rr.x), ry = sigm(rr.y);
            float zx = sigm(zz.x), zy = sigm(zz.y);
            float nx = tanhf(ni.x + rx * nh.x);
            float ny = tanhf(ni.y + ry * nh.y);
            float hx = featT[c * 16 + 2 * p];
            float hy = featT[c * 16 + 2 * p + 1];
            hn[2 * p]     = nx + zx * (hx - nx);
            hn[2 * p + 1] = ny + zy * (hy - ny);
        }
        {   // store own col locally + to stage (no reader conflicts remain)
            float4* dl = reinterpret_cast<float4*>(featT + c * 16);
            float4* ds = reinterpret_cast<float4*>(g_hstage[bid] + t * 16);
            const float4* hv = reinterpret_cast<const float4*>(hn);
#pragma unroll
            for (int i = 0; i < 4; ++i) { dl[i] = hv[i]; ds[i] = hv[i]; }
        }
        __threadfence();
        CLUSTER_SYNC();                          // sync #2: h visible
        {   // copy peer's h half
            const float4* src = reinterpret_cast<const float4*>(g_hstage[bid ^ 1] + t * 16);
            float4* dst = reinterpret_cast<float4*>(featT + (((rank ^ 1) * 256) + t) * 16);
#pragma unroll
            for (int i = 0; i < 4; ++i) dst[i] = src[i];
        }
        __syncthreads();

        do_heads(featT, red, out, b0, step + 1, rank, bmu, blv);
    }
}

// ---------------------------------------------------------------------------
extern "C" void kernel_launch(void* const* d_in, const int* in_sizes, int n_in,
                              void* d_out, int out_size) {
    const float* xl  = (const float*)d_in[0];   // x_l_seq   [1024,168,64]
    const float* xe  = (const float*)d_in[1];   // x_ext_seq [1024,168,16]
    const float* z   = (const float*)d_in[2];   // z_latent  [1024,512]
    const float* Wih = (const float*)d_in[3];   // [1536,256]
    const float* Whh = (const float*)d_in[4];   // [1536,512]
    const float* bih = (const float*)d_in[5];   // [1536]
    const float* bhh = (const float*)d_in[6];   // [1536]
    const float* Wmu = (const float*)d_in[7];   // [24,512]
    const float* bmu = (const float*)d_in[8];   // [24]
    const float* Wlv = (const float*)d_in[9];   // [24,512]
    const float* blv = (const float*)d_in[10];  // [24]
    const float* Wtb = (const float*)d_in[11];  // [592,256]
    const float* btb = (const float*)d_in[12];  // [256]
    float* out = (float*)d_out;                 // mu [1024,169,24] then lv

    const int smem_bytes = (FEAT * TB + XPDIM * TB + 4096) * 4;  // 70656
    cudaFuncSetAttribute((const void*)decoder_kernel,
                         cudaFuncAttributeMaxDynamicSharedMemorySize, smem_bytes);

    prep_kernel<<<256, 256>>>(Wih, Whh, Wmu, Wlv, Wtb);
    decoder_kernel<<<NCTA, NT, smem_bytes>>>(xl, xe, z, bih, bhh, bmu, blv, btb, out);
}

// round 15
// speedup vs baseline: 1.0006x; 1.0005x over previous
#include <cuda_runtime.h>
#include <math.h>

// ---------------------------------------------------------------------------
// VariationalDecoder: 168-step GRU decoder, B=1024, H=512, XP=256.
// 64 clusters x 2 CTAs x 256 threads. TB=16 batch rows per cluster.
// Each CTA owns 256 of 512 gate columns (1 col/thread, 3 gates, 16 rows).
// Doubles arithmetic intensity vs TB=8 (the measured L1tex-wavefront wall).
// h / x_prime halves exchanged via global staging + cluster.sync (2/step).
// ---------------------------------------------------------------------------

#define L_STEPS 168
#define BATCH   1024
#define HDIM    512
#define XPDIM   256
#define XLDIM   64
#define XEDIM   16
#define FEAT    592
#define TB      16
#define NCTA    128           // 64 clusters x 2
#define NT      256
#define OUTL    169
#define OUTC    24
#define OUT_ROW (OUTL * OUTC)            // 4056
#define NMU     ((size_t)BATCH * OUT_ROW)

// combined gate weights, k2-major: m<256 -> Whh k2=m; 256..383 -> Wih; pad 4.
// [m][jj=1536] float2 = {W[jj][2m], W[jj][2m+1]}
__device__ float2 g_WgC[388 * 1536];
// GEMM1: [q=148][n=256] float4 = rows 4q..4q+3 of Wtb for col n
__device__ float4 g_WtbP4[148 * 256];
// heads: [k2=256][oo=48] float2 (mu 0..23, lv 24..47)
__device__ float2 g_WhP[256 * 48];
// cross-CTA staging (per CTA: its OWN halves, read by the peer)
__device__ float g_hstage[NCTA][256 * 16];
__device__ float g_xstage[NCTA][128 * 16];

typedef unsigned long long u64;

__device__ __forceinline__ u64 ffma2(u64 a, u64 b, u64 c) {
    u64 d;
    asm("fma.rn.f32x2 %0, %1, %2, %3;" : "=l"(d) : "l"(a), "l"(b), "l"(c));
    return d;
}
__device__ __forceinline__ u64 splat2(float x) {
    u64 d;
    asm("mov.b64 %0, {%1, %1};" : "=l"(d) : "f"(x));
    return d;
}
__device__ __forceinline__ float2 unpack2(u64 v) {
    float2 f;
    asm("mov.b64 {%0, %1}, %2;" : "=f"(f.x), "=f"(f.y) : "l"(v));
    return f;
}
__device__ __forceinline__ float sigm(float x) { return 1.0f / (1.0f + expf(-x)); }

#define CLUSTER_SYNC() do { \
    asm volatile("barrier.cluster.arrive.aligned;" ::: "memory"); \
    asm volatile("barrier.cluster.wait.aligned;" ::: "memory"); \
} while (0)

// ---------------------------------------------------------------------------
// Prep (once per launch)
// ---------------------------------------------------------------------------
__global__ void prep_kernel(const float* __restrict__ Wih,
                            const float* __restrict__ Whh,
                            const float* __restrict__ Wmu,
                            const float* __restrict__ Wlv,
                            const float* __restrict__ Wtb) {
    int stride = gridDim.x * blockDim.x;
    int tid = blockIdx.x * blockDim.x + threadIdx.x;
    for (int idx = tid; idx < 388 * 1536; idx += stride) {
        int m = idx / 1536, jj = idx % 1536;
        float2 v = make_float2(0.f, 0.f);
        if (m < 256) {
            v = make_float2(Whh[jj * HDIM + 2 * m], Whh[jj * HDIM + 2 * m + 1]);
        } else if (m < 384) {
            int k2 = m - 256;
            v = make_float2(Wih[jj * XPDIM + 2 * k2], Wih[jj * XPDIM + 2 * k2 + 1]);
        }
        g_WgC[idx] = v;
    }
    for (int idx = tid; idx < 148 * 256; idx += stride) {
        int q = idx / 256, n = idx % 256;
        g_WtbP4[idx] = make_float4(Wtb[(4 * q) * XPDIM + n], Wtb[(4 * q + 1) * XPDIM + n],
                                   Wtb[(4 * q + 2) * XPDIM + n], Wtb[(4 * q + 3) * XPDIM + n]);
    }
    for (int idx = tid; idx < 256 * 48; idx += stride) {
        int k2 = idx / 48, oo = idx % 48;
        const float* Wh = (oo < 24) ? (Wmu + oo * HDIM) : (Wlv + (oo - 24) * HDIM);
        g_WhP[idx] = make_float2(Wh[2 * k2], Wh[2 * k2 + 1]);
    }
}

// ---------------------------------------------------------------------------
// FMA helpers: 8 FFMA2 = 16 rows x one weight scalar
// ---------------------------------------------------------------------------
__device__ __forceinline__ void fma8(const ulonglong2 (&F)[4], u64 w, u64 (&a)[8]) {
#pragma unroll
    for (int i = 0; i < 4; ++i) {
        a[2 * i]     = ffma2(F[i].x, w, a[2 * i]);
        a[2 * i + 1] = ffma2(F[i].y, w, a[2 * i + 1]);
    }
}
__device__ __forceinline__ void loadF(const float*& f, ulonglong2 (&F)[4]) {
#pragma unroll
    for (int i = 0; i < 4; ++i) F[i] = reinterpret_cast<const ulonglong2*>(f)[i];
    f += 16;
}

__device__ __forceinline__ void loadwb(float2 (&wb)[2][3], const float2* w) {
#pragma unroll
    for (int q = 0; q < 2; ++q)
#pragma unroll
        for (int g = 0; g < 3; ++g) wb[q][g] = w[q * 1536 + g * 512];
}

// one block = 2 k2 = 4 k rows, 3 gates, 16 batch rows (96 FFMA2)
__device__ __forceinline__ void proc2_16(const float*& f, const float2 (&wb)[2][3],
                                         u64 (&aR)[8], u64 (&aZ)[8], u64 (&aN)[8]) {
#pragma unroll
    for (int q = 0; q < 2; ++q) {
        ulonglong2 F0[4], F1[4];
        loadF(f, F0);
        loadF(f, F1);
        fma8(F0, splat2(wb[q][0].x), aR); fma8(F1, splat2(wb[q][0].y), aR);
        fma8(F0, splat2(wb[q][1].x), aZ); fma8(F1, splat2(wb[q][1].y), aZ);
        fma8(F0, splat2(wb[q][2].x), aN); fma8(F1, splat2(wb[q][2].y), aN);
    }
}

// GEMM1: one float4 = 4 k rows for this thread's column (32 FFMA2)
__device__ __forceinline__ void proc_q16(const float*& f, float4 wq, u64 (&a)[8]) {
    float wv[4] = {wq.x, wq.y, wq.z, wq.w};
#pragma unroll
    for (int kk = 0; kk < 4; ++kk) {
        ulonglong2 F[4];
        loadF(f, F);
        fma8(F, splat2(wv[kk]), a);
    }
}

// ---------------------------------------------------------------------------
// Heads: rank0 -> mu, rank1 -> lv. 192 thr: o=t%24, p=t/24 (8 K-partitions).
// Caller guarantees a preceding __syncthreads-equivalent barrier.
// ---------------------------------------------------------------------------
__device__ __forceinline__ void do_heads(const float* featT, float* red,
                                         float* __restrict__ out, int b0, int tstep,
                                         int rank,
                                         const float* __restrict__ bmu,
                                         const float* __restrict__ blv) {
    int t = threadIdx.x;
    if (t < 192) {
        int o = t % 24;
        int p = t / 24;
        u64 a[8];
#pragma unroll
        for (int i = 0; i < 8; ++i) a[i] = 0ull;
        const float2* w = g_WhP + (p * 32) * 48 + (rank * 24 + o);
        const float* f = featT + (p * 64) * 16;
#pragma unroll 2
        for (int k2 = 0; k2 < 32; ++k2) {
            ulonglong2 F0[4], F1[4];
            loadF(f, F0);
            loadF(f, F1);
            float2 wv = *w;
            fma8(F0, splat2(wv.x), a);
            fma8(F1, splat2(wv.y), a);
            w += 48;
        }
        u64* rp = reinterpret_cast<u64*>(red + t * 16);
#pragma unroll
        for (int i = 0; i < 8; ++i) rp[i] = a[i];
    }
    __syncthreads();
    if (t < 24) {
        float bias = rank ? blv[t] : bmu[t];
        float* obase = out + (rank ? NMU : 0) + (size_t)tstep * 24 + t;
#pragma unroll
        for (int r = 0; r < TB; ++r) {
            float s = bias;
#pragma unroll
            for (int p = 0; p < 8; ++p)
                s += red[(p * 24 + t) * 16 + r];
            obase[(size_t)(b0 + r) * OUT_ROW] = s;
        }
    }
}

// ---------------------------------------------------------------------------
// Main persistent kernel (cluster of 2 CTAs per batch group of 16)
// ---------------------------------------------------------------------------
extern "C" __global__ void __launch_bounds__(NT, 1) __cluster_dims__(2, 1, 1)
decoder_kernel(const float* __restrict__ xl, const float* __restrict__ xe,
               const float* __restrict__ z,
               const float* __restrict__ bih, const float* __restrict__ bhh,
               const float* __restrict__ bmu, const float* __restrict__ blv,
               const float* __restrict__ btb,
               float* __restrict__ out) {
    extern __shared__ __align__(16) float smem[];
    float* featT = smem;                         // [592][16] = 9472 floats
    float* xpT   = smem + FEAT * TB;             // [256][16] = 4096 floats
    float* red   = smem + FEAT * TB + XPDIM * TB;// 4096 floats

    const int t    = threadIdx.x;                // 0..255
    const int bid  = blockIdx.x;
    const int rank = bid & 1;
    const int b0   = (bid >> 1) * TB;
    const int c    = rank * 256 + t;             // gate column (0..511)

    // fused biases
    const float brz_r = bih[c]       + bhh[c];
    const float brz_z = bih[512 + c] + bhh[512 + c];
    const float bn_i  = bih[1024 + c];
    const float bn_h  = bhh[1024 + c];
    // GEMM1 split-K mapping: col j, K-half h1
    const int j1 = rank * 128 + (t & 127);
    const int h1 = t >> 7;
    const float btb_n = btb[rank * 128 + (t < 128 ? t : t - 128)];

    // featT <- z (each CTA loads full 512 cols of its 16 rows)
#pragma unroll
    for (int m = 0; m < 32; ++m) {
        int idx = t + NT * m;                    // 0..8191
        int r = idx >> 9, k = idx & 511;
        featT[k * 16 + r] = z[(size_t)(b0 + r) * HDIM + k];
    }
    __syncthreads();
    do_heads(featT, red, out, b0, 0, rank, bmu, blv);    // slot 0

    for (int step = 0; step < L_STEPS; ++step) {
        // ---- xl/xe tails ------------------------------------------------
#pragma unroll
        for (int m = 0; m < 4; ++m) {
            int idx = t + NT * m;                // 0..1023
            int r = idx >> 6, i = idx & 63;
            featT[(HDIM + i) * 16 + r] =
                xl[((size_t)(b0 + r) * L_STEPS + step) * XLDIM + i];
        }
        {
            int r = t >> 4, i = t & 15;          // 256 values
            featT[(HDIM + XLDIM + i) * 16 + r] =
                xe[((size_t)(b0 + r) * L_STEPS + step) * XEDIM + i];
        }
        __syncthreads();   // tails ready; also orders heads-red vs gemm1-red

        // ---- GEMM1 split-K x2 on own 128 cols ---------------------------
        {
            u64 a[8];
#pragma unroll
            for (int i = 0; i < 8; ++i) a[i] = 0ull;
            const float4* w = g_WtbP4 + (size_t)h1 * 74 * 256 + j1;
            const float* f = featT + h1 * 296 * 16;
            float4 wA = w[0], wB = w[256];
            w += 512;
#pragma unroll 1
            for (int q = 0; q < 72; q += 2) {
                float4 wC = w[0], wD = w[256];
                w += 512;
                proc_q16(f, wA, a);
                proc_q16(f, wB, a);
                wA = wC; wB = wD;
            }
            proc_q16(f, wA, a);
            proc_q16(f, wB, a);
            u64* rp = reinterpret_cast<u64*>(red + t * 16);
#pragma unroll
            for (int i = 0; i < 8; ++i) rp[i] = a[i];
        }
        __syncthreads();
        if (t < 128) {   // reduce halves, tanh, own xpT cols + stage
            float* dst = xpT + (rank * 128 + t) * 16;
            float* stg = g_xstage[bid] + t * 16;
#pragma unroll
            for (int r = 0; r < 16; ++r) {
                float s = red[t * 16 + r] + red[(128 + t) * 16 + r] + btb_n;
                float v = tanhf(s);
                dst[r] = v;
                stg[r] = v;
            }
        }
        __threadfence();   // xstage visible before sync #1 (taken mid-step)

        // ---- gates: hh phase first (K=512 over h) -----------------------
        u64 aR[8], aZ[8], aNi[8], aNh[8];
        {
            u64 br = splat2(brz_r), bz = splat2(brz_z), bn = splat2(bn_h);
#pragma unroll
            for (int p = 0; p < 8; ++p) { aR[p] = br; aZ[p] = bz; aNh[p] = bn; }
        }
        const float2* w = g_WgC + c;             // row stride 1536
        float2 wA[2][3], wB[2][3];
        loadwb(wA, w); w += 3072;
        {
            const float* f = featT;
#pragma unroll 1
            for (int bb = 0; bb < 64; ++bb) {    // 128 blocks = 256 k2
                loadwb(wB, w); w += 3072;
                proc2_16(f, wA, aR, aZ, aNh);
                loadwb(wA, w); w += 3072;
                proc2_16(f, wB, aR, aZ, aNh);
            }
            // wA now holds the first ih block (combined array, seamless)
        }

        // ---- exchange x_prime halves ------------------------------------
        CLUSTER_SYNC();                          // sync #1: xp visible
        if (t < 128) {
            const float4* src = reinterpret_cast<const float4*>(g_xstage[bid ^ 1] + t * 16);
            float4* dst = reinterpret_cast<float4*>(xpT + (((rank ^ 1) * 128) + t) * 16);
#pragma unroll
            for (int i = 0; i < 4; ++i) dst[i] = src[i];
        }
        __syncthreads();

        // ---- gates: ih phase (K=256 over x_prime) -----------------------
        {
            u64 bn = splat2(bn_i);
#pragma unroll
            for (int p = 0; p < 8; ++p) aNi[p] = bn;
        }
        {
            const float* f = xpT;
#pragma unroll 1
            for (int bb = 0; bb < 32; ++bb) {    // 64 blocks = 128 k2 (+pad)
                loadwb(wB, w); w += 3072;
                proc2_16(f, wA, aR, aZ, aNi);
                loadwb(wA, w); w += 3072;
                proc2_16(f, wB, aR, aZ, aNi);
            }
        }

        // ---- nonlinearity + h_new (own column c) ------------------------
        float hn[16];
#pragma unroll
        for (int p = 0; p < 8; ++p) {
            float2 rr = unpack2(aR[p]);
            float2 zz = unpack2(aZ[p]);
            float2 ni = unpack2(aNi[p]);
            float2 nh = unpack2(aNh[p]);
            float rx = sigm(rr.x), ry = sigm(rr.y);
            float zx = sigm(zz.x), zy = sigm(zz.y);
            float nx = tanhf(ni.x + rx * nh.x);
            float ny = tanhf(ni.y + ry * nh.y);
            float hx = featT[c * 16 + 2 * p];
            float hy = featT[c * 16 + 2 * p + 1];
            hn[2 * p]     = nx + zx * (hx - nx);
            hn[2 * p + 1] = ny + zy * (hy - ny);
        }
        {   // store own col locally + to stage (no reader conflicts remain)
            float4* dl = reinterpret_cast<float4*>(featT + c * 16);
            float4* ds = reinterpret_cast<float4*>(g_hstage[bid] + t * 16);
            const float4* hv = reinterpret_cast<const float4*>(hn);
#pragma unroll
            for (int i = 0; i < 4; ++i) { dl[i] = hv[i]; ds[i] = hv[i]; }
        }
        __threadfence();
        CLUSTER_SYNC();                          // sync #2: h visible
        {   // copy peer's h half
            const float4* src = reinterpret_cast<const float4*>(g_hstage[bid ^ 1] + t * 16);
            float4* dst = reinterpret_cast<float4*>(featT + (((rank ^ 1) * 256) + t) * 16);
#pragma unroll
            for (int i = 0; i < 4; ++i) dst[i] = src[i];
        }
        __syncthreads();

        do_heads(featT, red, out, b0, step + 1, rank, bmu, blv);
    }
}

// ---------------------------------------------------------------------------
extern "C" void kernel_launch(void* const* d_in, const int* in_sizes, int n_in,
                              void* d_out, int out_size) {
    const float* xl  = (const float*)d_in[0];   // x_l_seq   [1024,168,64]
    const float* xe  = (const float*)d_in[1];   // x_ext_seq [1024,168,16]
    const float* z   = (const float*)d_in[2];   // z_latent  [1024,512]
    const float* Wih = (const float*)d_in[3];   // [1536,256]
    const float* Whh = (const float*)d_in[4];   // [1536,512]
    const float* bih = (const float*)d_in[5];   // [1536]
    const float* bhh = (const float*)d_in[6];   // [1536]
    const float* Wmu = (const float*)d_in[7];   // [24,512]
    const float* bmu = (const float*)d_in[8];   // [24]
    const float* Wlv = (const float*)d_in[9];   // [24,512]
    const float* blv = (const float*)d_in[10];  // [24]
    const float* Wtb = (const float*)d_in[11];  // [592,256]
    const float* btb = (const float*)d_in[12];  // [256]
    float* out = (float*)d_out;                 // mu [1024,169,24] then lv

    const int smem_bytes = (FEAT * TB + XPDIM * TB + 4096) * 4;  // 70656
    cudaFuncSetAttribute((const void*)decoder_kernel,
                         cudaFuncAttributeMaxDynamicSharedMemorySize, smem_bytes);

    prep_kernel<<<256, 256>>>(Wih, Whh, Wmu, Wlv, Wtb);
    decoder_kernel<<<NCTA, NT, smem_bytes>>>(xl, xe, z, bih, bhh, bmu, blv, btb, out);
}